// round 9
// baseline (speedup 1.0000x reference)
#include <cuda_runtime.h>
#include <cuda_bf16.h>
#include <math.h>

#define BATCH   512
#define T_STEPS 512
#define CHAN    32
#define CIN     33
#define HID     128
#define GATES   512   // 4*H
#define EPSF    1e-12f

typedef unsigned long long ull_t;

// ---------------------------------------------------------------------------
// f32x2 packed-math helpers (Blackwell FFMA2 path — only reachable via PTX)
// ---------------------------------------------------------------------------
__device__ __forceinline__ void ffma2(ull_t& d, ull_t a, ull_t b) {
    asm("fma.rn.f32x2 %0, %1, %2, %0;" : "+l"(d) : "l"(a), "l"(b));
}
// (bf16_lo, bf16_hi) packed in u32 -> (f32_lo, f32_hi) packed b64 (pure ALU)
__device__ __forceinline__ ull_t bf2_to_f32x2(unsigned int u) {
    ull_t r;
    asm("{\n\t.reg .b32 lo, hi;\n\t"
        "shl.b32 lo, %1, 16;\n\t"
        "and.b32 hi, %1, 0xFFFF0000;\n\t"
        "mov.b64 %0, {lo, hi};\n\t}" : "=l"(r) : "r"(u));
    return r;
}
__device__ __forceinline__ ull_t pack_dup(float v) {
    ull_t r; unsigned int b = __float_as_uint(v);
    asm("mov.b64 %0, {%1, %1};" : "=l"(r) : "r"(b));
    return r;
}
__device__ __forceinline__ float2 unpack2(ull_t d) {
    unsigned int lo, hi;
    asm("mov.b64 {%0, %1}, %2;" : "=r"(lo), "=r"(hi) : "l"(d));
    return make_float2(__uint_as_float(lo), __uint_as_float(hi));
}
__device__ __forceinline__ float hsum2(ull_t d) {
    float2 f = unpack2(d); return f.x + f.y;
}
__device__ __forceinline__ unsigned int pack_bf2(float a, float b) {
    unsigned int ua = (unsigned int)__bfloat16_as_ushort(__float2bfloat16(a));
    unsigned int ub = (unsigned int)__bfloat16_as_ushort(__float2bfloat16(b));
    return ua | (ub << 16);
}

// ---------------------------------------------------------------------------
// Device scratch (static; allocations are forbidden)
// ---------------------------------------------------------------------------
__device__ float        g_std_arr[T_STEPS];             // minibatch-std scalar per t
__device__ float        g_inv_arr[4];                   // 1/sigma: ih, hh, fc
__device__ float        g_wt[CIN * GATES];              // Wih^T scaled: [33][512]
__device__ float        g_bias[GATES];                  // b_ih + b_hh
__device__ unsigned int g_whh_q[(HID / 4) * GATES * 2]; // bf16 k-quads: [32 k4][512 g][2]
__device__ float        g_gates[(size_t)BATCH * T_STEPS * GATES]; // 536 MB gates_x

// ---------------------------------------------------------------------------
// Kernel A: minibatch std feature. grid=T, block=256 (8 b-seg x 32 chan)
// ---------------------------------------------------------------------------
__global__ void std_kernel(const float* __restrict__ x)
{
    int t   = blockIdx.x;
    int tid = threadIdx.x;
    int c   = tid & 31;
    int seg = tid >> 5;

    float s = 0.f, ss = 0.f;
    for (int b = seg; b < BATCH; b += 8) {
        float v = x[((size_t)b * T_STEPS + t) * CHAN + c];
        s  += v;
        ss += v * v;
    }
    __shared__ float sm1[256], sm2[256];
    sm1[tid] = s; sm2[tid] = ss;
    __syncthreads();
    if (seg == 0) {
        for (int k = 1; k < 8; k++) { s += sm1[k * 32 + c]; ss += sm2[k * 32 + c]; }
        float mean = s * (1.f / 512.f);
        float var  = (ss - 512.f * mean * mean) * (1.f / 511.f);
        float sd   = sqrtf(fmaxf(var, 0.f));
        #pragma unroll
        for (int off = 16; off; off >>= 1)
            sd += __shfl_xor_sync(0xffffffffu, sd, off);
        if (c == 0) g_std_arr[t] = sd * (1.f / 32.f);
    }
}

// ---------------------------------------------------------------------------
// Kernel B: spectral norms (one power iteration, matching reference exactly)
// then scale+transpose Wih, combine bias, quantize Whh to bf16 k-quads.
// single block, 512 threads
// ---------------------------------------------------------------------------
__global__ void prep_kernel(const float* __restrict__ wih, const float* __restrict__ uih,
                            const float* __restrict__ whh, const float* __restrict__ uhh,
                            const float* __restrict__ bih, const float* __restrict__ bhh,
                            const float* __restrict__ wfc, const float* __restrict__ ufc)
{
    __shared__ float tv[HID];
    __shared__ float red[512];
    __shared__ float nrm;
    __shared__ float inv_s[4];
    int tid = threadIdx.x;

    // ---- ih: W [512,33] ----
    if (tid < CIN) {
        float s = 0.f;
        for (int g = 0; g < GATES; g++) s += wih[g * CIN + tid] * uih[g];
        tv[tid] = s;
    }
    __syncthreads();
    if (tid == 0) {
        float n = 0.f;
        for (int c = 0; c < CIN; c++) n += tv[c] * tv[c];
        nrm = sqrtf(n) + EPSF;
    }
    __syncthreads();
    {
        float a = 0.f;
        for (int c = 0; c < CIN; c++) a += wih[tid * CIN + c] * tv[c];
        a /= nrm;
        red[tid] = a * a;
    }
    __syncthreads();
    for (int off = 256; off; off >>= 1) {
        if (tid < off) red[tid] += red[tid + off];
        __syncthreads();
    }
    if (tid == 0) {
        float ssum = red[0];                      // ||W v||^2
        float v = (sqrtf(ssum) + EPSF) / ssum;    // 1/sigma
        g_inv_arr[0] = v; inv_s[0] = v;
    }
    __syncthreads();

    // ---- hh: W [512,128] ----
    if (tid < HID) {
        float s = 0.f;
        for (int g = 0; g < GATES; g++) s += whh[g * HID + tid] * uhh[g];
        tv[tid] = s;
    }
    __syncthreads();
    if (tid == 0) {
        float n = 0.f;
        for (int k = 0; k < HID; k++) n += tv[k] * tv[k];
        nrm = sqrtf(n) + EPSF;
    }
    __syncthreads();
    {
        float a = 0.f;
        for (int k = 0; k < HID; k++) a += whh[tid * HID + k] * tv[k];
        a /= nrm;
        red[tid] = a * a;
    }
    __syncthreads();
    for (int off = 256; off; off >>= 1) {
        if (tid < off) red[tid] += red[tid + off];
        __syncthreads();
    }
    if (tid == 0) {
        float ssum = red[0];
        float v = (sqrtf(ssum) + EPSF) / ssum;
        g_inv_arr[1] = v; inv_s[1] = v;
    }
    __syncthreads();

    // ---- fc: W [1,128] ----
    red[tid] = (tid < HID) ? wfc[tid] * wfc[tid] : 0.f;
    __syncthreads();
    for (int off = 256; off; off >>= 1) {
        if (tid < off) red[tid] += red[tid + off];
        __syncthreads();
    }
    if (tid == 0) {
        float wn2 = red[0];
        float u0  = ufc[0];
        float tn  = fabsf(u0) * sqrtf(wn2) + EPSF;   // ||W^T u||
        float s   = u0 * wn2 / tn;                   // W @ v (scalar)
        float sig = s * s / (fabsf(s) + EPSF);
        float v = 1.f / sig;
        g_inv_arr[2] = v; inv_s[2] = v;
    }
    __syncthreads();

    // ---- scale + pack ----
    float i0 = inv_s[0], i1 = inv_s[1];
    // Wih transposed & scaled: g_wt[c*512+g]
    for (int c = 0; c < CIN; c++)
        g_wt[c * GATES + tid] = wih[tid * CIN + c] * i0;
    g_bias[tid] = bih[tid] + bhh[tid];
    // Whh scaled -> bf16 k-quads: g_whh_q[k4*1024 + g*2 + {0,1}]
    for (int k4 = 0; k4 < HID / 4; k4++) {
        float w0 = whh[tid * HID + 4 * k4]     * i1;
        float w1 = whh[tid * HID + 4 * k4 + 1] * i1;
        float w2 = whh[tid * HID + 4 * k4 + 2] * i1;
        float w3 = whh[tid * HID + 4 * k4 + 3] * i1;
        g_whh_q[k4 * (GATES * 2) + tid * 2]     = pack_bf2(w0, w1);
        g_whh_q[k4 * (GATES * 2) + tid * 2 + 1] = pack_bf2(w2, w3);
    }
}

// ---------------------------------------------------------------------------
// Kernel C: gates_x = x_aug @ Wih_n^T + bias (f32x2 packed over gate pairs).
// grid = 8192 blocks x 32 rows, 256 threads; thread t owns gates (2t, 2t+1).
// ---------------------------------------------------------------------------
__global__ void gates_kernel(const float* __restrict__ x)
{
    __shared__ ull_t xs_d[CIN * 34];   // x duplicated (v,v), [c][34 rows]
    int row0 = blockIdx.x * 32;
    int tid  = threadIdx.x;

    for (int i = tid; i < 32 * CHAN; i += 256) {
        int r = i >> 5, c = i & 31;
        xs_d[c * 34 + r] = pack_dup(x[(size_t)(row0 + r) * CHAN + c]);
    }
    if (tid < 32)
        xs_d[CHAN * 34 + tid] = pack_dup(g_std_arr[(row0 + tid) & (T_STEPS - 1)]);
    __syncthreads();

    const ull_t* wt2   = (const ull_t*)g_wt;     // (w_2t, w_2t+1) f32 pairs
    const ull_t* bias2 = (const ull_t*)g_bias;
    ull_t*       gout  = (ull_t*)g_gates;
    ull_t bp = bias2[tid];

    for (int rb = 0; rb < 32; rb += 8) {
        ull_t acc[8];
        #pragma unroll
        for (int r = 0; r < 8; r++) acc[r] = bp;
        #pragma unroll
        for (int c = 0; c < CIN; c++) {
            ull_t w = wt2[c * (GATES / 2) + tid];
            #pragma unroll
            for (int r = 0; r < 8; r++)
                ffma2(acc[r], w, xs_d[c * 34 + rb + r]);
        }
        #pragma unroll
        for (int r = 0; r < 8; r++)
            gout[(size_t)(row0 + rb + r) * (GATES / 2) + tid] = acc[r];
    }
}

// ---------------------------------------------------------------------------
// Kernel D: persistent LSTM + online-softmax attention + FC epilogue.
// 128 blocks x 4 batch rows, 512 threads, 512 steps.
// Whh lives in REGISTERS: thread t holds gate t's 128 bf16 weights as 32 ull.
// Matvec: f32x2 over k-parity, h via LDS.128 broadcast (1 wavefront each).
// Pointwise: thread t owns slot (r = t>>7, j = t&127); softmax state in regs.
// ---------------------------------------------------------------------------
__global__ void __launch_bounds__(512, 1)
lstm_kernel(const float* __restrict__ attn_w,
            const float* __restrict__ fc_w,
            const float* __restrict__ fc_b,
            float* __restrict__ out)
{
    __shared__ __align__(16) float h_s[4 * HID];   // [4][128]
    __shared__ float gts[4 * GATES];               // [4][512]
    __shared__ float aw_s[HID];
    __shared__ float fw_s[HID];
    __shared__ float lpart[16];                    // per-warp attn partials

    int tid  = threadIdx.x;
    int b0   = blockIdx.x * 4;
    int wid  = tid >> 5, lane = tid & 31;
    int r_pw = tid >> 7, j_pw = tid & 127;

    // ---- weights into registers: 32 ull (64 regs), coalesced LDG.64 ----
    ull_t wreg[HID / 4];
    {
        const ull_t* wq = (const ull_t*)g_whh_q;   // [32 k4][512 g] ull
        #pragma unroll
        for (int k4 = 0; k4 < HID / 4; k4++)
            wreg[k4] = wq[k4 * GATES + tid];
    }

    if (tid < 4 * HID) h_s[tid] = 0.f;
    if (tid < HID) { aw_s[tid] = attn_w[tid]; fw_s[tid] = fc_w[tid]; }
    __syncthreads();

    float cst  = 0.f;          // cell state for slot (r_pw, j_pw)
    float accp = 0.f;          // online pooled accumulator for slot
    float mloc = -INFINITY;    // softmax running max for row r_pw (redundant/thread)
    float sloc = 0.f;          // softmax running sum for row r_pw

    const float4* h4   = (const float4*)h_s;       // [4][32] float4
    const float*  gsrc = g_gates;

    for (int t = 0; t < T_STEPS; t++) {
        // prefetch gates_x (coalesced; latency hidden under the matvec)
        float gx[4];
        #pragma unroll
        for (int r = 0; r < 4; r++)
            gx[r] = gsrc[((size_t)(b0 + r) * T_STEPS + t) * GATES + tid];

        // gates += h @ Whh^T   (4 rows, 1 gate/thread, weights in regs)
        ull_t a[4] = {0, 0, 0, 0};
        #pragma unroll
        for (int k4 = 0; k4 < HID / 4; k4++) {
            unsigned int wlo = (unsigned int)wreg[k4];
            unsigned int whi = (unsigned int)(wreg[k4] >> 32);
            ull_t w0 = bf2_to_f32x2(wlo);          // k = 4k4, 4k4+1
            ull_t w1 = bf2_to_f32x2(whi);          // k = 4k4+2, 4k4+3
            #pragma unroll
            for (int r = 0; r < 4; r++) {
                float4 hv = h4[r * (HID / 4) + k4];   // LDS.128 broadcast (1 wf)
                ull_t h01, h23;
                asm("mov.b64 %0, {%2, %3}; mov.b64 %1, {%4, %5};"
                    : "=l"(h01), "=l"(h23)
                    : "r"(__float_as_uint(hv.x)), "r"(__float_as_uint(hv.y)),
                      "r"(__float_as_uint(hv.z)), "r"(__float_as_uint(hv.w)));
                ffma2(a[r], w0, h01);
                ffma2(a[r], w1, h23);
            }
        }
        #pragma unroll
        for (int r = 0; r < 4; r++)
            gts[r * GATES + tid] = hsum2(a[r]) + gx[r];
        __syncthreads();                            // sync1: gates ready

        // pointwise LSTM cell (1 slot/thread); exp-based activations
        const float* gr = &gts[r_pw * GATES];
        float gi = gr[j_pw], gf = gr[HID + j_pw];
        float gg = gr[2 * HID + j_pw], go = gr[3 * HID + j_pw];
        float iv = 1.f / (1.f + __expf(-gi));
        float fv = 1.f / (1.f + __expf(-gf));
        float gv = 2.f / (1.f + __expf(-2.f * gg)) - 1.f;    // tanh
        float ov = 1.f / (1.f + __expf(-go));
        float c  = fv * cst + iv * gv;
        cst      = c;
        float hv = ov * (2.f / (1.f + __expf(-2.f * c)) - 1.f);
        h_s[r_pw * HID + j_pw] = hv;

        // attention partial: per-warp shuffle reduce of h*aw
        float part = hv * aw_s[j_pw];
        #pragma unroll
        for (int off = 16; off; off >>= 1)
            part += __shfl_xor_sync(0xffffffffu, part, off);
        if (lane == 0) lpart[wid] = part;
        __syncthreads();                            // sync2: h + partials ready

        // online softmax, state in registers (redundant per thread of a row)
        float l = lpart[r_pw * 4] + lpart[r_pw * 4 + 1]
                + lpart[r_pw * 4 + 2] + lpart[r_pw * 4 + 3];
        float mnew = fmaxf(mloc, l);
        float al   = __expf(mloc - mnew);           // 0 on first step
        float pv   = __expf(l - mnew);
        mloc = mnew;
        sloc = sloc * al + pv;
        accp = accp * al + pv * hv;
        // hazards: h_s written before sync2(t), read after sync2(t) by matvec;
        // gts read before sync2(t), rewritten after; lpart read here, next
        // write is after sync1(t+1). Two barriers/step suffice.
    }

    // epilogue: pooled = acc/s ; score = pooled . (fc_w/sigma) + fc_b
    __syncthreads();                                // protect lpart reuse
    float po   = accp / sloc;
    float part = po * fw_s[j_pw];
    #pragma unroll
    for (int off = 16; off; off >>= 1)
        part += __shfl_xor_sync(0xffffffffu, part, off);
    if (lane == 0) lpart[wid] = part;
    __syncthreads();
    if (tid < 4) {
        float sc = lpart[tid * 4] + lpart[tid * 4 + 1]
                 + lpart[tid * 4 + 2] + lpart[tid * 4 + 3];
        out[b0 + tid] = sc * g_inv_arr[2] + fc_b[0];
    }
}

// ---------------------------------------------------------------------------
extern "C" void kernel_launch(void* const* d_in, const int* in_sizes, int n_in,
                              void* d_out, int out_size)
{
    const float* x      = (const float*)d_in[0];
    const float* w_ih   = (const float*)d_in[1];
    const float* u_ih   = (const float*)d_in[2];
    const float* w_hh   = (const float*)d_in[3];
    const float* u_hh   = (const float*)d_in[4];
    const float* b_ih   = (const float*)d_in[5];
    const float* b_hh   = (const float*)d_in[6];
    const float* attn_w = (const float*)d_in[7];
    // d_in[8] = attn_b (softmax shift-invariant, unused)
    const float* fc_w   = (const float*)d_in[9];
    const float* u_fc   = (const float*)d_in[10];
    const float* fc_b   = (const float*)d_in[11];
    float* out = (float*)d_out;

    std_kernel<<<T_STEPS, 256>>>(x);
    prep_kernel<<<1, 512>>>(w_ih, u_ih, w_hh, u_hh, b_ih, b_hh, fc_w, u_fc);
    gates_kernel<<<(BATCH * T_STEPS) / 32, 256>>>(x);
    lstm_kernel<<<BATCH / 4, 512>>>(attn_w, fc_w, fc_b, out);
}

// round 11
// speedup vs baseline: 1.3242x; 1.3242x over previous
#include <cuda_runtime.h>
#include <cuda_bf16.h>
#include <math.h>

#define BATCH   512
#define T_STEPS 512
#define CHAN    32
#define CIN     33
#define HID     128
#define GATES   512   // 4*H
#define EPSF    1e-12f

typedef unsigned long long ull_t;
typedef unsigned int u32_t;

// ---------------------------------------------------------------------------
// f32x2 packed-math helpers (Blackwell FFMA2 path — only reachable via PTX)
// ---------------------------------------------------------------------------
__device__ __forceinline__ void ffma2(ull_t& d, ull_t a, ull_t b) {
    asm("fma.rn.f32x2 %0, %1, %2, %0;" : "+l"(d) : "l"(a), "l"(b));
}
// (bf16_lo, bf16_hi) packed in u32 -> (f32_lo, f32_hi) packed b64 (pure ALU)
__device__ __forceinline__ ull_t bf2_to_f32x2(u32_t u) {
    ull_t r;
    asm("{\n\t.reg .b32 lo, hi;\n\t"
        "shl.b32 lo, %1, 16;\n\t"
        "and.b32 hi, %1, 0xFFFF0000;\n\t"
        "mov.b64 %0, {lo, hi};\n\t}" : "=l"(r) : "r"(u));
    return r;
}
__device__ __forceinline__ ull_t pack_dup(float v) {
    ull_t r; u32_t b = __float_as_uint(v);
    asm("mov.b64 %0, {%1, %1};" : "=l"(r) : "r"(b));
    return r;
}
__device__ __forceinline__ float2 unpack2(ull_t d) {
    u32_t lo, hi;
    asm("mov.b64 {%0, %1}, %2;" : "=r"(lo), "=r"(hi) : "l"(d));
    return make_float2(__uint_as_float(lo), __uint_as_float(hi));
}
__device__ __forceinline__ float hsum2(ull_t d) {
    float2 f = unpack2(d); return f.x + f.y;
}
__device__ __forceinline__ u32_t pack_bf2(float a, float b) {
    u32_t ua = (u32_t)__bfloat16_as_ushort(__float2bfloat16(a));
    u32_t ub = (u32_t)__bfloat16_as_ushort(__float2bfloat16(b));
    return ua | (ub << 16);
}
__device__ __forceinline__ ull_t pack2(float a, float b) {
    ull_t r;
    asm("mov.b64 %0, {%1, %2};" : "=l"(r)
        : "r"(__float_as_uint(a)), "r"(__float_as_uint(b)));
    return r;
}

// ---------------------------------------------------------------------------
// Device scratch (static; allocations are forbidden)
// ---------------------------------------------------------------------------
__device__ float g_std_arr[T_STEPS];             // minibatch-std scalar per t
__device__ float g_inv_arr[4];                   // 1/sigma: ih, hh, fc
__device__ float g_wt[CIN * GATES];              // Wih^T scaled: [33][512]
__device__ float g_bias[GATES];                  // b_ih + b_hh
__device__ u32_t g_whh_q[(HID / 4) * GATES * 2]; // bf16 k-quads: [32 k4][512 g][2]
__device__ float g_gates[(size_t)BATCH * T_STEPS * GATES]; // 536 MB gates_x

// ---------------------------------------------------------------------------
// Kernel A: minibatch std feature. grid=T, block=256 (8 b-seg x 32 chan)
// ---------------------------------------------------------------------------
__global__ void std_kernel(const float* __restrict__ x)
{
    int t   = blockIdx.x;
    int tid = threadIdx.x;
    int c   = tid & 31;
    int seg = tid >> 5;

    float s = 0.f, ss = 0.f;
    for (int b = seg; b < BATCH; b += 8) {
        float v = x[((size_t)b * T_STEPS + t) * CHAN + c];
        s  += v;
        ss += v * v;
    }
    __shared__ float sm1[256], sm2[256];
    sm1[tid] = s; sm2[tid] = ss;
    __syncthreads();
    if (seg == 0) {
        for (int k = 1; k < 8; k++) { s += sm1[k * 32 + c]; ss += sm2[k * 32 + c]; }
        float mean = s * (1.f / 512.f);
        float var  = (ss - 512.f * mean * mean) * (1.f / 511.f);
        float sd   = sqrtf(fmaxf(var, 0.f));
        #pragma unroll
        for (int off = 16; off; off >>= 1)
            sd += __shfl_xor_sync(0xffffffffu, sd, off);
        if (c == 0) g_std_arr[t] = sd * (1.f / 32.f);
    }
}

// ---------------------------------------------------------------------------
// Kernel B: spectral norms (one power iteration, matching reference exactly)
// then scale+transpose Wih, combine bias, quantize Whh to bf16 k-quads.
// single block, 512 threads
// ---------------------------------------------------------------------------
__global__ void prep_kernel(const float* __restrict__ wih, const float* __restrict__ uih,
                            const float* __restrict__ whh, const float* __restrict__ uhh,
                            const float* __restrict__ bih, const float* __restrict__ bhh,
                            const float* __restrict__ wfc, const float* __restrict__ ufc)
{
    __shared__ float tv[HID];
    __shared__ float red[512];
    __shared__ float nrm;
    __shared__ float inv_s[4];
    int tid = threadIdx.x;

    // ---- ih: W [512,33] ----
    if (tid < CIN) {
        float s = 0.f;
        for (int g = 0; g < GATES; g++) s += wih[g * CIN + tid] * uih[g];
        tv[tid] = s;
    }
    __syncthreads();
    if (tid == 0) {
        float n = 0.f;
        for (int c = 0; c < CIN; c++) n += tv[c] * tv[c];
        nrm = sqrtf(n) + EPSF;
    }
    __syncthreads();
    {
        float a = 0.f;
        for (int c = 0; c < CIN; c++) a += wih[tid * CIN + c] * tv[c];
        a /= nrm;
        red[tid] = a * a;
    }
    __syncthreads();
    for (int off = 256; off; off >>= 1) {
        if (tid < off) red[tid] += red[tid + off];
        __syncthreads();
    }
    if (tid == 0) {
        float ssum = red[0];                      // ||W v||^2
        float v = (sqrtf(ssum) + EPSF) / ssum;    // 1/sigma
        g_inv_arr[0] = v; inv_s[0] = v;
    }
    __syncthreads();

    // ---- hh: W [512,128] ----
    if (tid < HID) {
        float s = 0.f;
        for (int g = 0; g < GATES; g++) s += whh[g * HID + tid] * uhh[g];
        tv[tid] = s;
    }
    __syncthreads();
    if (tid == 0) {
        float n = 0.f;
        for (int k = 0; k < HID; k++) n += tv[k] * tv[k];
        nrm = sqrtf(n) + EPSF;
    }
    __syncthreads();
    {
        float a = 0.f;
        for (int k = 0; k < HID; k++) a += whh[tid * HID + k] * tv[k];
        a /= nrm;
        red[tid] = a * a;
    }
    __syncthreads();
    for (int off = 256; off; off >>= 1) {
        if (tid < off) red[tid] += red[tid + off];
        __syncthreads();
    }
    if (tid == 0) {
        float ssum = red[0];
        float v = (sqrtf(ssum) + EPSF) / ssum;
        g_inv_arr[1] = v; inv_s[1] = v;
    }
    __syncthreads();

    // ---- fc: W [1,128] ----
    red[tid] = (tid < HID) ? wfc[tid] * wfc[tid] : 0.f;
    __syncthreads();
    for (int off = 256; off; off >>= 1) {
        if (tid < off) red[tid] += red[tid + off];
        __syncthreads();
    }
    if (tid == 0) {
        float wn2 = red[0];
        float u0  = ufc[0];
        float tn  = fabsf(u0) * sqrtf(wn2) + EPSF;   // ||W^T u||
        float s   = u0 * wn2 / tn;                   // W @ v (scalar)
        float sig = s * s / (fabsf(s) + EPSF);
        float v = 1.f / sig;
        g_inv_arr[2] = v; inv_s[2] = v;
    }
    __syncthreads();

    // ---- scale + pack ----
    float i0 = inv_s[0], i1 = inv_s[1];
    // Wih transposed & scaled: g_wt[c*512+g]
    for (int c = 0; c < CIN; c++)
        g_wt[c * GATES + tid] = wih[tid * CIN + c] * i0;
    g_bias[tid] = bih[tid] + bhh[tid];
    // Whh scaled -> bf16 k-quads: g_whh_q[k4*1024 + g*2 + {0,1}]
    for (int k4 = 0; k4 < HID / 4; k4++) {
        float w0 = whh[tid * HID + 4 * k4]     * i1;
        float w1 = whh[tid * HID + 4 * k4 + 1] * i1;
        float w2 = whh[tid * HID + 4 * k4 + 2] * i1;
        float w3 = whh[tid * HID + 4 * k4 + 3] * i1;
        g_whh_q[k4 * (GATES * 2) + tid * 2]     = pack_bf2(w0, w1);
        g_whh_q[k4 * (GATES * 2) + tid * 2 + 1] = pack_bf2(w2, w3);
    }
}

// ---------------------------------------------------------------------------
// Kernel C: gates_x = x_aug @ Wih_n^T + bias (f32x2 packed over gate pairs).
// grid = 8192 blocks x 32 rows, 256 threads; thread t owns gates (2t, 2t+1).
// ---------------------------------------------------------------------------
__global__ void gates_kernel(const float* __restrict__ x)
{
    __shared__ ull_t xs_d[CIN * 34];   // x duplicated (v,v), [c][34 rows]
    int row0 = blockIdx.x * 32;
    int tid  = threadIdx.x;

    for (int i = tid; i < 32 * CHAN; i += 256) {
        int r = i >> 5, c = i & 31;
        xs_d[c * 34 + r] = pack_dup(x[(size_t)(row0 + r) * CHAN + c]);
    }
    if (tid < 32)
        xs_d[CHAN * 34 + tid] = pack_dup(g_std_arr[(row0 + tid) & (T_STEPS - 1)]);
    __syncthreads();

    const ull_t* wt2   = (const ull_t*)g_wt;     // (w_2t, w_2t+1) f32 pairs
    const ull_t* bias2 = (const ull_t*)g_bias;
    ull_t*       gout  = (ull_t*)g_gates;
    ull_t bp = bias2[tid];

    for (int rb = 0; rb < 32; rb += 8) {
        ull_t acc[8];
        #pragma unroll
        for (int r = 0; r < 8; r++) acc[r] = bp;
        #pragma unroll
        for (int c = 0; c < CIN; c++) {
            ull_t w = wt2[c * (GATES / 2) + tid];
            #pragma unroll
            for (int r = 0; r < 8; r++)
                ffma2(acc[r], w, xs_d[c * 34 + rb + r]);
        }
        #pragma unroll
        for (int r = 0; r < 8; r++)
            gout[(size_t)(row0 + rb + r) * (GATES / 2) + tid] = acc[r];
    }
}

// ---------------------------------------------------------------------------
// Kernel D: persistent LSTM + online-softmax attention + FC epilogue.
// 128 blocks x 4 batch rows, 256 THREADS (reg cap 256/thread), 512 steps.
// Whh in REGISTERS: thread t holds gates t and t+256 (2 x 32 ull = 128 regs).
// Matvec: f32x2 over k-parity, h via LDS.128 broadcast (only smem traffic).
// Pointwise: 2 slots/thread: (r0=tid>>7, j), (r0+2, j) with j = tid&127.
// Softmax/cell state in registers. Two barriers per step.
// ---------------------------------------------------------------------------
__global__ void __launch_bounds__(256, 1)
lstm_kernel(const float* __restrict__ attn_w,
            const float* __restrict__ fc_w,
            const float* __restrict__ fc_b,
            float* __restrict__ out)
{
    __shared__ __align__(16) float h_s[4 * HID];   // [4][128]
    __shared__ float gts[4 * GATES];               // [4][512]
    __shared__ float aw_s[HID];
    __shared__ float fw_s[HID];
    __shared__ float lpart[2][8];                  // [slot][warp] attn partials

    int tid  = threadIdx.x;
    int b0   = blockIdx.x * 4;
    int wid  = tid >> 5, lane = tid & 31;
    int r0   = tid >> 7;          // slot0 row (0..1); slot1 row = r0+2
    int j0   = tid & 127;         // hidden index for both slots

    // ---- weights into registers: 2 gates x 32 ull = 128 regs, coalesced ----
    ull_t wreg0[HID / 4], wreg1[HID / 4];
    {
        const ull_t* wq = (const ull_t*)g_whh_q;   // [32 k4][512 g] ull
        #pragma unroll
        for (int k4 = 0; k4 < HID / 4; k4++) {
            wreg0[k4] = wq[k4 * GATES + tid];
            wreg1[k4] = wq[k4 * GATES + tid + 256];
        }
    }

    for (int i = tid; i < 4 * HID; i += 256) h_s[i] = 0.f;
    if (tid < HID) { aw_s[tid] = attn_w[tid]; fw_s[tid] = fc_w[tid]; }
    __syncthreads();

    float cst[2]  = {0.f, 0.f};           // cell state per slot
    float accp[2] = {0.f, 0.f};           // online pooled accumulator per slot
    float mloc[2] = {-INFINITY, -INFINITY};
    float sloc[2] = {0.f, 0.f};

    const float4* h4   = (const float4*)h_s;       // [4][32] float4
    const float*  gsrc = g_gates;

    for (int t = 0; t < T_STEPS; t++) {
        // prefetch gates_x (coalesced; latency hidden under the matvec)
        float gx0[4], gx1[4];
        #pragma unroll
        for (int r = 0; r < 4; r++) {
            size_t base = ((size_t)(b0 + r) * T_STEPS + t) * GATES;
            gx0[r] = gsrc[base + tid];
            gx1[r] = gsrc[base + tid + 256];
        }

        // gates += h @ Whh^T  (2 gates x 4 rows, weights in registers)
        ull_t a0[4] = {0, 0, 0, 0};
        ull_t a1[4] = {0, 0, 0, 0};
        #pragma unroll
        for (int k4 = 0; k4 < HID / 4; k4++) {
            ull_t w0 = wreg0[k4], w1 = wreg1[k4];
            ull_t w0lo = bf2_to_f32x2((u32_t)w0);
            ull_t w0hi = bf2_to_f32x2((u32_t)(w0 >> 32));
            ull_t w1lo = bf2_to_f32x2((u32_t)w1);
            ull_t w1hi = bf2_to_f32x2((u32_t)(w1 >> 32));
            #pragma unroll
            for (int r = 0; r < 4; r++) {
                float4 hv = h4[r * (HID / 4) + k4];    // LDS.128 broadcast
                ull_t h01 = pack2(hv.x, hv.y);
                ull_t h23 = pack2(hv.z, hv.w);
                ffma2(a0[r], w0lo, h01);
                ffma2(a0[r], w0hi, h23);
                ffma2(a1[r], w1lo, h01);
                ffma2(a1[r], w1hi, h23);
            }
        }
        #pragma unroll
        for (int r = 0; r < 4; r++) {
            gts[r * GATES + tid]       = hsum2(a0[r]) + gx0[r];
            gts[r * GATES + tid + 256] = hsum2(a1[r]) + gx1[r];
        }
        __syncthreads();                            // sync1: gates ready

        // pointwise LSTM cell, 2 slots/thread; exp-based activations
        float hv2[2];
        #pragma unroll
        for (int p = 0; p < 2; p++) {
            int r = r0 + 2 * p;
            const float* gr = &gts[r * GATES];
            float gi = gr[j0], gf = gr[HID + j0];
            float gg = gr[2 * HID + j0], go = gr[3 * HID + j0];
            float iv = 1.f / (1.f + __expf(-gi));
            float fv = 1.f / (1.f + __expf(-gf));
            float gv = 2.f / (1.f + __expf(-2.f * gg)) - 1.f;   // tanh
            float ov = 1.f / (1.f + __expf(-go));
            float c  = fv * cst[p] + iv * gv;
            cst[p]   = c;
            float hv = ov * (2.f / (1.f + __expf(-2.f * c)) - 1.f);
            hv2[p]   = hv;
            h_s[r * HID + j0] = hv;
        }

        // attention partials: per (warp, slot) a clean 32-j segment of one row
        #pragma unroll
        for (int p = 0; p < 2; p++) {
            float part = hv2[p] * aw_s[j0];
            #pragma unroll
            for (int off = 16; off; off >>= 1)
                part += __shfl_xor_sync(0xffffffffu, part, off);
            if (lane == 0) lpart[p][wid] = part;
        }
        __syncthreads();                            // sync2: h + partials ready

        // online softmax, state in registers (redundant across a row's threads)
        #pragma unroll
        for (int p = 0; p < 2; p++) {
            int r  = r0 + 2 * p;                    // row of this slot
            int ws = 4 * (r & 1);                   // warps holding this row
            float l = lpart[p][ws] + lpart[p][ws + 1]
                    + lpart[p][ws + 2] + lpart[p][ws + 3];
            float mnew = fmaxf(mloc[p], l);
            float al   = __expf(mloc[p] - mnew);    // 0 on first step
            float pv   = __expf(l - mnew);
            mloc[p] = mnew;
            sloc[p] = sloc[p] * al + pv;
            accp[p] = accp[p] * al + pv * hv2[p];
        }
        // hazards: h_s written pre-sync2, read by matvec(t+1) pre-sync1(t+1) ✓;
        // gts read pre-sync2, rewritten post-sync2 ✓; lpart read here post-
        // sync2, next written post-sync1(t+1) ✓. Two barriers/step suffice.
    }

    // epilogue: pooled = acc/s ; score = pooled . (fc_w/sigma) + fc_b
    __syncthreads();                                // lpart reads done, reuse
    #pragma unroll
    for (int p = 0; p < 2; p++) {
        float po   = accp[p] / sloc[p];
        float part = po * fw_s[j0];
        #pragma unroll
        for (int off = 16; off; off >>= 1)
            part += __shfl_xor_sync(0xffffffffu, part, off);
        if (lane == 0) lpart[p][wid] = part;
    }
    __syncthreads();
    if (tid < 4) {
        int p  = tid >> 1;                          // slot that owns row tid
        int ws = 4 * (tid & 1);
        float sc = lpart[p][ws] + lpart[p][ws + 1]
                 + lpart[p][ws + 2] + lpart[p][ws + 3];
        out[b0 + tid] = sc * g_inv_arr[2] + fc_b[0];
    }
}

// ---------------------------------------------------------------------------
extern "C" void kernel_launch(void* const* d_in, const int* in_sizes, int n_in,
                              void* d_out, int out_size)
{
    const float* x      = (const float*)d_in[0];
    const float* w_ih   = (const float*)d_in[1];
    const float* u_ih   = (const float*)d_in[2];
    const float* w_hh   = (const float*)d_in[3];
    const float* u_hh   = (const float*)d_in[4];
    const float* b_ih   = (const float*)d_in[5];
    const float* b_hh   = (const float*)d_in[6];
    const float* attn_w = (const float*)d_in[7];
    // d_in[8] = attn_b (softmax shift-invariant, unused)
    const float* fc_w   = (const float*)d_in[9];
    const float* u_fc   = (const float*)d_in[10];
    const float* fc_b   = (const float*)d_in[11];
    float* out = (float*)d_out;

    std_kernel<<<T_STEPS, 256>>>(x);
    prep_kernel<<<1, 512>>>(w_ih, u_ih, w_hh, u_hh, b_ih, b_hh, fc_w, u_fc);
    gates_kernel<<<(BATCH * T_STEPS) / 32, 256>>>(x);
    lstm_kernel<<<BATCH / 4, 256>>>(attn_w, fc_w, fc_b, out);
}

// round 13
// speedup vs baseline: 2.2758x; 1.7187x over previous
#include <cuda_runtime.h>
#include <cuda_bf16.h>
#include <math.h>

#define BATCH   512
#define T_STEPS 512
#define CHAN    32
#define CIN     33
#define HID     128
#define GATES   512   // 4*H
#define EPSF    1e-12f

typedef unsigned long long ull_t;
typedef unsigned int u32_t;

// ---------------------------------------------------------------------------
// f32x2 packed-math helpers (Blackwell FFMA2 path — only reachable via PTX)
// ---------------------------------------------------------------------------
__device__ __forceinline__ void ffma2(ull_t& d, ull_t a, ull_t b) {
    asm("fma.rn.f32x2 %0, %1, %2, %0;" : "+l"(d) : "l"(a), "l"(b));
}
// (bf16_lo, bf16_hi) packed in u32 -> (f32_lo, f32_hi) packed b64 (pure ALU)
__device__ __forceinline__ ull_t bf2_to_f32x2(u32_t u) {
    ull_t r;
    asm("{\n\t.reg .b32 lo, hi;\n\t"
        "shl.b32 lo, %1, 16;\n\t"
        "and.b32 hi, %1, 0xFFFF0000;\n\t"
        "mov.b64 %0, {lo, hi};\n\t}" : "=l"(r) : "r"(u));
    return r;
}
__device__ __forceinline__ ull_t pack_dup(float v) {
    ull_t r; u32_t b = __float_as_uint(v);
    asm("mov.b64 %0, {%1, %1};" : "=l"(r) : "r"(b));
    return r;
}
__device__ __forceinline__ float2 unpack2(ull_t d) {
    u32_t lo, hi;
    asm("mov.b64 {%0, %1}, %2;" : "=r"(lo), "=r"(hi) : "l"(d));
    return make_float2(__uint_as_float(lo), __uint_as_float(hi));
}
__device__ __forceinline__ float hsum2(ull_t d) {
    float2 f = unpack2(d); return f.x + f.y;
}
__device__ __forceinline__ u32_t pack_bf2(float a, float b) {
    u32_t ua = (u32_t)__bfloat16_as_ushort(__float2bfloat16(a));
    u32_t ub = (u32_t)__bfloat16_as_ushort(__float2bfloat16(b));
    return ua | (ub << 16);
}
__device__ __forceinline__ ull_t pack2(float a, float b) {
    ull_t r;
    asm("mov.b64 %0, {%1, %2};" : "=l"(r)
        : "r"(__float_as_uint(a)), "r"(__float_as_uint(b)));
    return r;
}

// ---------------------------------------------------------------------------
// Device scratch (static; allocations are forbidden)
// ---------------------------------------------------------------------------
__device__ float g_std_arr[T_STEPS];             // minibatch-std scalar per t
__device__ float g_inv_arr[4];                   // 1/sigma: ih, hh, fc
__device__ float g_wt[CIN * GATES];              // Wih^T scaled: [33][512]
__device__ float g_bias[GATES];                  // b_ih + b_hh
__device__ u32_t g_whh_p[(HID / 2) * GATES];     // bf16 k-pairs, k2-major [64][512]
__device__ float g_gates[(size_t)BATCH * T_STEPS * GATES]; // 536 MB gates_x

// ---------------------------------------------------------------------------
// Kernel A: minibatch std feature. grid=T, block=256 (8 b-seg x 32 chan)
// ---------------------------------------------------------------------------
__global__ void std_kernel(const float* __restrict__ x)
{
    int t   = blockIdx.x;
    int tid = threadIdx.x;
    int c   = tid & 31;
    int seg = tid >> 5;

    float s = 0.f, ss = 0.f;
    for (int b = seg; b < BATCH; b += 8) {
        float v = x[((size_t)b * T_STEPS + t) * CHAN + c];
        s  += v;
        ss += v * v;
    }
    __shared__ float sm1[256], sm2[256];
    sm1[tid] = s; sm2[tid] = ss;
    __syncthreads();
    if (seg == 0) {
        for (int k = 1; k < 8; k++) { s += sm1[k * 32 + c]; ss += sm2[k * 32 + c]; }
        float mean = s * (1.f / 512.f);
        float var  = (ss - 512.f * mean * mean) * (1.f / 511.f);
        float sd   = sqrtf(fmaxf(var, 0.f));
        #pragma unroll
        for (int off = 16; off; off >>= 1)
            sd += __shfl_xor_sync(0xffffffffu, sd, off);
        if (c == 0) g_std_arr[t] = sd * (1.f / 32.f);
    }
}

// ---------------------------------------------------------------------------
// Kernel B: spectral norms (one power iteration, matching reference exactly)
// then scale+transpose Wih, combine bias, quantize Whh to bf16 k-pairs.
// single block, 512 threads
// ---------------------------------------------------------------------------
__global__ void prep_kernel(const float* __restrict__ wih, const float* __restrict__ uih,
                            const float* __restrict__ whh, const float* __restrict__ uhh,
                            const float* __restrict__ bih, const float* __restrict__ bhh,
                            const float* __restrict__ wfc, const float* __restrict__ ufc)
{
    __shared__ float tv[HID];
    __shared__ float red[512];
    __shared__ float nrm;
    __shared__ float inv_s[4];
    int tid = threadIdx.x;

    // ---- ih: W [512,33] ----
    if (tid < CIN) {
        float s = 0.f;
        for (int g = 0; g < GATES; g++) s += wih[g * CIN + tid] * uih[g];
        tv[tid] = s;
    }
    __syncthreads();
    if (tid == 0) {
        float n = 0.f;
        for (int c = 0; c < CIN; c++) n += tv[c] * tv[c];
        nrm = sqrtf(n) + EPSF;
    }
    __syncthreads();
    {
        float a = 0.f;
        for (int c = 0; c < CIN; c++) a += wih[tid * CIN + c] * tv[c];
        a /= nrm;
        red[tid] = a * a;
    }
    __syncthreads();
    for (int off = 256; off; off >>= 1) {
        if (tid < off) red[tid] += red[tid + off];
        __syncthreads();
    }
    if (tid == 0) {
        float ssum = red[0];                      // ||W v||^2
        float v = (sqrtf(ssum) + EPSF) / ssum;    // 1/sigma
        g_inv_arr[0] = v; inv_s[0] = v;
    }
    __syncthreads();

    // ---- hh: W [512,128] ----
    if (tid < HID) {
        float s = 0.f;
        for (int g = 0; g < GATES; g++) s += whh[g * HID + tid] * uhh[g];
        tv[tid] = s;
    }
    __syncthreads();
    if (tid == 0) {
        float n = 0.f;
        for (int k = 0; k < HID; k++) n += tv[k] * tv[k];
        nrm = sqrtf(n) + EPSF;
    }
    __syncthreads();
    {
        float a = 0.f;
        for (int k = 0; k < HID; k++) a += whh[tid * HID + k] * tv[k];
        a /= nrm;
        red[tid] = a * a;
    }
    __syncthreads();
    for (int off = 256; off; off >>= 1) {
        if (tid < off) red[tid] += red[tid + off];
        __syncthreads();
    }
    if (tid == 0) {
        float ssum = red[0];
        float v = (sqrtf(ssum) + EPSF) / ssum;
        g_inv_arr[1] = v; inv_s[1] = v;
    }
    __syncthreads();

    // ---- fc: W [1,128] ----
    red[tid] = (tid < HID) ? wfc[tid] * wfc[tid] : 0.f;
    __syncthreads();
    for (int off = 256; off; off >>= 1) {
        if (tid < off) red[tid] += red[tid + off];
        __syncthreads();
    }
    if (tid == 0) {
        float wn2 = red[0];
        float u0  = ufc[0];
        float tn  = fabsf(u0) * sqrtf(wn2) + EPSF;   // ||W^T u||
        float s   = u0 * wn2 / tn;                   // W @ v (scalar)
        float sig = s * s / (fabsf(s) + EPSF);
        float v = 1.f / sig;
        g_inv_arr[2] = v; inv_s[2] = v;
    }
    __syncthreads();

    // ---- scale + pack ----
    float i0 = inv_s[0], i1 = inv_s[1];
    // Wih transposed & scaled: g_wt[c*512+g]
    for (int c = 0; c < CIN; c++)
        g_wt[c * GATES + tid] = wih[tid * CIN + c] * i0;
    g_bias[tid] = bih[tid] + bhh[tid];
    // Whh scaled -> bf16 k-pairs, k2-major: g_whh_p[k2*512 + g]
    for (int k2 = 0; k2 < HID / 2; k2++) {
        float we = whh[tid * HID + 2 * k2]     * i1;
        float wo = whh[tid * HID + 2 * k2 + 1] * i1;
        g_whh_p[k2 * GATES + tid] = pack_bf2(we, wo);
    }
}

// ---------------------------------------------------------------------------
// Kernel C: gates_x = x_aug @ Wih_n^T + bias (f32x2 packed over gate pairs).
// grid = 8192 blocks x 32 rows, 256 threads; thread t owns gates (2t, 2t+1).
// ---------------------------------------------------------------------------
__global__ void gates_kernel(const float* __restrict__ x)
{
    __shared__ ull_t xs_d[CIN * 34];   // x duplicated (v,v), [c][34 rows]
    int row0 = blockIdx.x * 32;
    int tid  = threadIdx.x;

    for (int i = tid; i < 32 * CHAN; i += 256) {
        int r = i >> 5, c = i & 31;
        xs_d[c * 34 + r] = pack_dup(x[(size_t)(row0 + r) * CHAN + c]);
    }
    if (tid < 32)
        xs_d[CHAN * 34 + tid] = pack_dup(g_std_arr[(row0 + tid) & (T_STEPS - 1)]);
    __syncthreads();

    const ull_t* wt2   = (const ull_t*)g_wt;     // (w_2t, w_2t+1) f32 pairs
    const ull_t* bias2 = (const ull_t*)g_bias;
    ull_t*       gout  = (ull_t*)g_gates;
    ull_t bp = bias2[tid];

    for (int rb = 0; rb < 32; rb += 8) {
        ull_t acc[8];
        #pragma unroll
        for (int r = 0; r < 8; r++) acc[r] = bp;
        #pragma unroll
        for (int c = 0; c < CIN; c++) {
            ull_t w = wt2[c * (GATES / 2) + tid];
            #pragma unroll
            for (int r = 0; r < 8; r++)
                ffma2(acc[r], w, xs_d[c * 34 + rb + r]);
        }
        #pragma unroll
        for (int r = 0; r < 8; r++)
            gout[(size_t)(row0 + rb + r) * (GATES / 2) + tid] = acc[r];
    }
}

// ---------------------------------------------------------------------------
// Kernel D: persistent LSTM + online-softmax attention + FC epilogue.
// 128 blocks x 4 batch rows, 256 threads, 512 steps.
// R6-proven layout: thread t owns gates (2t, 2t+1); matvec f32x2 over
// k-parity; h via LDS.64 broadcast. HYBRID weights: k2 0..31 in 64 regs,
// k2 32..63 from smem (halves weight-LDS). Two barriers/step (R10-proven),
// exp-form activations, softmax state in registers.
// ---------------------------------------------------------------------------
__global__ void __launch_bounds__(256, 1)
lstm_kernel(const float* __restrict__ attn_w,
            const float* __restrict__ fc_w,
            const float* __restrict__ fc_b,
            float* __restrict__ out)
{
    extern __shared__ __align__(16) unsigned char smem_raw[];
    ull_t* wsm = (ull_t*)smem_raw;                 // [32 k2][256] ull (k2 32..63)

    __shared__ __align__(16) float h_s[4 * HID];   // [4][128]
    __shared__ float gts[4 * GATES];               // [4][512]
    __shared__ float aw_s[HID];
    __shared__ float fw_s[HID];
    __shared__ float lpart[2][8];                  // [slot][warp] attn partials

    int tid  = threadIdx.x;
    int b0   = blockIdx.x * 4;
    int wid  = tid >> 5, lane = tid & 31;
    int r0   = tid >> 7;          // slot0 row (0..1); slot1 row = r0+2
    int j0   = tid & 127;         // hidden index for both slots

    const ull_t* gwp = (const ull_t*)g_whh_p;      // [64 k2][256] ull (gate pairs)

    // weights: k2 0..31 into registers (64 regs), k2 32..63 into smem
    ull_t wreg[32];
    #pragma unroll
    for (int k2 = 0; k2 < 32; k2++)
        wreg[k2] = gwp[k2 * (GATES / 2) + tid];
    for (int i = tid; i < 32 * (GATES / 2); i += 256)
        wsm[i] = gwp[32 * (GATES / 2) + i];

    for (int i = tid; i < 4 * HID; i += 256) h_s[i] = 0.f;
    if (tid < HID) { aw_s[tid] = attn_w[tid]; fw_s[tid] = fc_w[tid]; }
    __syncthreads();

    float cst[2]  = {0.f, 0.f};           // cell state per slot
    float accp[2] = {0.f, 0.f};           // online pooled accumulator per slot
    float mloc[2] = {-INFINITY, -INFINITY};
    float sloc[2] = {0.f, 0.f};

    const ull_t* h8   = (const ull_t*)h_s;         // (h[2k2], h[2k2+1]) f32 pairs
    const ull_t* gsrc = (const ull_t*)g_gates;
    ull_t*       gts2 = (ull_t*)gts;

    for (int t = 0; t < T_STEPS; t++) {
        // prefetch gates_x pairs (coalesced; latency hidden under the matvec)
        ull_t gx[4];
        #pragma unroll
        for (int r = 0; r < 4; r++)
            gx[r] = gsrc[((size_t)(b0 + r) * T_STEPS + t) * (GATES / 2) + tid];

        // gates += h @ Whh^T  (acc = (sum_even_k, sum_odd_k) per gate)
        ull_t a0[4] = {0, 0, 0, 0};   // gate 2t
        ull_t a1[4] = {0, 0, 0, 0};   // gate 2t+1
        #pragma unroll
        for (int k2 = 0; k2 < 32; k2++) {           // register half
            float2 wb = unpack2(wreg[k2]);
            ull_t w0 = bf2_to_f32x2(__float_as_uint(wb.x));
            ull_t w1 = bf2_to_f32x2(__float_as_uint(wb.y));
            #pragma unroll
            for (int r = 0; r < 4; r++) {
                ull_t hv = h8[r * (HID / 2) + k2];  // LDS.64 broadcast
                ffma2(a0[r], w0, hv);
                ffma2(a1[r], w1, hv);
            }
        }
        #pragma unroll 16
        for (int k2 = 32; k2 < 64; k2++) {          // smem half
            ull_t wpair = wsm[(k2 - 32) * (GATES / 2) + tid];  // LDS.64
            float2 wb = unpack2(wpair);
            ull_t w0 = bf2_to_f32x2(__float_as_uint(wb.x));
            ull_t w1 = bf2_to_f32x2(__float_as_uint(wb.y));
            #pragma unroll
            for (int r = 0; r < 4; r++) {
                ull_t hv = h8[r * (HID / 2) + k2];
                ffma2(a0[r], w0, hv);
                ffma2(a1[r], w1, hv);
            }
        }
        #pragma unroll
        for (int r = 0; r < 4; r++) {
            float2 gxf = unpack2(gx[r]);
            gts2[r * (GATES / 2) + tid] =
                pack2(hsum2(a0[r]) + gxf.x, hsum2(a1[r]) + gxf.y);  // STS.64
        }
        __syncthreads();                            // sync1: gates ready

        // pointwise LSTM cell, 2 slots/thread; exp-based activations
        float hv2[2];
        #pragma unroll
        for (int p = 0; p < 2; p++) {
            int r = r0 + 2 * p;
            const float* gr = &gts[r * GATES];
            float gi = gr[j0], gf = gr[HID + j0];
            float gg = gr[2 * HID + j0], go = gr[3 * HID + j0];
            float iv = 1.f / (1.f + __expf(-gi));
            float fv = 1.f / (1.f + __expf(-gf));
            float gv = 2.f / (1.f + __expf(-2.f * gg)) - 1.f;   // tanh
            float ov = 1.f / (1.f + __expf(-go));
            float c  = fv * cst[p] + iv * gv;
            cst[p]   = c;
            float hv = ov * (2.f / (1.f + __expf(-2.f * c)) - 1.f);
            hv2[p]   = hv;
            h_s[r * HID + j0] = hv;
        }

        // attention partials: per (warp, slot) a clean 32-j segment of one row
        #pragma unroll
        for (int p = 0; p < 2; p++) {
            float part = hv2[p] * aw_s[j0];
            #pragma unroll
            for (int off = 16; off; off >>= 1)
                part += __shfl_xor_sync(0xffffffffu, part, off);
            if (lane == 0) lpart[p][wid] = part;
        }
        __syncthreads();                            // sync2: h + partials ready

        // online softmax, state in registers (redundant across a row's threads)
        #pragma unroll
        for (int p = 0; p < 2; p++) {
            int r  = r0 + 2 * p;                    // row of this slot
            int ws = 4 * (r & 1);                   // warps holding this row
            float l = lpart[p][ws] + lpart[p][ws + 1]
                    + lpart[p][ws + 2] + lpart[p][ws + 3];
            float mnew = fmaxf(mloc[p], l);
            float al   = __expf(mloc[p] - mnew);    // 0 on first step
            float pv   = __expf(l - mnew);
            mloc[p] = mnew;
            sloc[p] = sloc[p] * al + pv;
            accp[p] = accp[p] * al + pv * hv2[p];
        }
        // hazards: h_s written pre-sync2, read by matvec(t+1) post-sync2 ✓;
        // gts read pre-sync2, rewritten post-sync2 ✓; lpart read here post-
        // sync2, next written post-sync1(t+1) ✓. Two barriers/step suffice.
    }

    // epilogue: pooled = acc/s ; score = pooled . (fc_w/sigma) + fc_b
    __syncthreads();                                // lpart reads done, reuse
    #pragma unroll
    for (int p = 0; p < 2; p++) {
        float po   = accp[p] / sloc[p];
        float part = po * fw_s[j0];
        #pragma unroll
        for (int off = 16; off; off >>= 1)
            part += __shfl_xor_sync(0xffffffffu, part, off);
        if (lane == 0) lpart[p][wid] = part;
    }
    __syncthreads();
    if (tid < 4) {
        int p  = tid >> 1;                          // slot that owns row tid
        int ws = 4 * (tid & 1);
        float sc = lpart[p][ws] + lpart[p][ws + 1]
                 + lpart[p][ws + 2] + lpart[p][ws + 3];
        out[b0 + tid] = sc * g_inv_arr[2] + fc_b[0];
    }
}

// ---------------------------------------------------------------------------
extern "C" void kernel_launch(void* const* d_in, const int* in_sizes, int n_in,
                              void* d_out, int out_size)
{
    const float* x      = (const float*)d_in[0];
    const float* w_ih   = (const float*)d_in[1];
    const float* u_ih   = (const float*)d_in[2];
    const float* w_hh   = (const float*)d_in[3];
    const float* u_hh   = (const float*)d_in[4];
    const float* b_ih   = (const float*)d_in[5];
    const float* b_hh   = (const float*)d_in[6];
    const float* attn_w = (const float*)d_in[7];
    // d_in[8] = attn_b (softmax shift-invariant, unused)
    const float* fc_w   = (const float*)d_in[9];
    const float* u_fc   = (const float*)d_in[10];
    const float* fc_b   = (const float*)d_in[11];
    float* out = (float*)d_out;

    std_kernel<<<T_STEPS, 256>>>(x);
    prep_kernel<<<1, 512>>>(w_ih, u_ih, w_hh, u_hh, b_ih, b_hh, fc_w, u_fc);
    gates_kernel<<<(BATCH * T_STEPS) / 32, 256>>>(x);

    int smem = 32 * (GATES / 2) * 8;   // 64 KB dynamic: smem half of Whh
    cudaFuncSetAttribute(lstm_kernel, cudaFuncAttributeMaxDynamicSharedMemorySize, smem);
    lstm_kernel<<<BATCH / 4, 256, smem>>>(attn_w, fc_w, fc_b, out);
}